// round 13
// baseline (speedup 1.0000x reference)
#include <cuda_runtime.h>
#include <cuda_bf16.h>

typedef unsigned long long u64;
typedef unsigned int u32;

#define HIDN 10
#define CCH  256
#define HWV  16384
#define NIMG 8
#define NPAIR 65536
#define NPIX 131072
// output offsets (floats)
#define OUT_XHL  1310720
#define OUT_ATTU 2621440
#define OUT_ATTL 2752512

// scratch: 22 planes of dots; float view [22][131072]
__device__ __align__(16) u64 g_hacc[22 * NPAIR];

// ---------- bf16 split / mma helpers (k1) ----------
__device__ __forceinline__ u32 bfb(float f) {
    return (u32)__bfloat16_as_ushort(__float2bfloat16(f));
}
__device__ __forceinline__ float bff(u32 u) {
    return __bfloat162float(__ushort_as_bfloat16((unsigned short)u));
}
__device__ __forceinline__ u32 prmt_hi(u32 a, u32 b) {
    u32 d; asm("prmt.b32 %0,%1,%2,0x7632;" : "=r"(d) : "r"(a), "r"(b)); return d;
}
__device__ __forceinline__ u32 cvt_bf2(float hi, float lo) {
    u32 d; asm("cvt.rn.bf16x2.f32 %0,%1,%2;" : "=r"(d) : "f"(hi), "f"(lo)); return d;
}
__device__ __forceinline__ float maskhi(u32 v) {
    return __uint_as_float(v & 0xFFFF0000u);
}
__device__ __forceinline__ void mma_bf16(float (&d)[4], const u32 (&a)[4], const u32* b) {
    asm volatile(
        "mma.sync.aligned.m16n8k16.row.col.f32.bf16.bf16.f32 "
        "{%0,%1,%2,%3},{%4,%5,%6,%7},{%8,%9},{%0,%1,%2,%3};"
        : "+f"(d[0]), "+f"(d[1]), "+f"(d[2]), "+f"(d[3])
        : "r"(a[0]), "r"(a[1]), "r"(a[2]), "r"(a[3]), "r"(b[0]), "r"(b[1]));
}
__device__ __forceinline__ void cp16(float* dst, const float* src) {
    u32 ds = (u32)__cvta_generic_to_shared(dst);
    asm volatile("cp.async.cg.shared.global [%0], [%1], 16;" :: "r"(ds), "l"(src));
}
#define CP_COMMIT() asm volatile("cp.async.commit_group;" ::: "memory")
#define CP_WAIT2()  asm volatile("cp.async.wait_group 2;" ::: "memory")

// ============================================================================
// Kernel 1 (tensor): hacc[22][pix] = W[22x256] . hfea[256][pix]
// bf16 hi/lo split (3 products, m16n8k16). Unchanged from R12.
// ============================================================================

#define HROW 264
#define HBUF (32 * HROW)
#define K1_STAGES 4
#define K1_SMEM_BYTES ((8192 + K1_STAGES * HBUF) * 4)

__global__ void __launch_bounds__(256) k1t_kernel(const float* __restrict__ hfea,
                                                  const float* __restrict__ w_pdp1,
                                                  const float* __restrict__ w_dua,
                                                  const float* __restrict__ w_dla) {
    extern __shared__ u32 smemu[];
    u32*   Whi  = smemu;
    u32*   Wlo  = smemu + 4096;
    float* hbuf = (float*)(smemu + 8192);

    const int tid = threadIdx.x;
    const int w   = tid >> 5;
    const int l   = tid & 31;
    const int bid = blockIdx.x;

    for (int sidx = tid; sidx < 1024; sidx += 256) {
        int t = sidx >> 9, rem = sidx & 511, s = rem >> 5, ln = rem & 31;
#pragma unroll
        for (int r = 0; r < 4; r++) {
            int row = 16 * t + (ln >> 2) + 8 * (r & 1);
            int k0  = 16 * s + (ln & 3) * 2 + 8 * (r >> 1);
            float v0 = 0.f, v1 = 0.f;
            if (row < 20)       { v0 = w_pdp1[row * 276 + k0]; v1 = w_pdp1[row * 276 + k0 + 1]; }
            else if (row == 20) { v0 = w_dua[k0]; v1 = w_dua[k0 + 1]; }
            else if (row == 21) { v0 = w_dla[k0]; v1 = w_dla[k0 + 1]; }
            u32 h0 = bfb(v0), h1 = bfb(v1);
            Whi[sidx * 4 + r] = (h1 << 16) | h0;
            float lo0 = v0 - bff(h0), lo1 = v1 - bff(h1);
            Wlo[sidx * 4 + r] = (bfb(lo1) << 16) | bfb(lo0);
        }
    }

    const int row  = tid >> 3;
    const int seg0 = tid & 7;
    auto issue_load = [&](int g) {
        const int c2  = bid + (g >> 3) * 128;
        const int n2  = c2 >> 6;
        const int hw2 = (c2 & 63) << 8;
        const int kk  = g & 7;
        const float* srcr = hfea + ((size_t)(n2 * CCH + kk * 32) + row) * HWV + hw2;
        float* dstr = hbuf + (g & 3) * HBUF + row * HROW;
#pragma unroll
        for (int j = 0; j < 8; j++) { int seg = seg0 + j * 8; cp16(dstr + seg * 4, srcr + seg * 4); }
    };

    issue_load(0); CP_COMMIT();
    issue_load(1); CP_COMMIT();
    issue_load(2); CP_COMMIT();
    __syncthreads();

    int gi = 0;
#pragma unroll 1
    for (int ci = 0; ci < 4; ci++) {
        const int c   = bid + ci * 128;
        const int n   = c >> 6;
        const int hw0 = (c & 63) << 8;

        float Cf[2][4][4];
#pragma unroll
        for (int t = 0; t < 2; t++)
#pragma unroll
            for (int nt = 0; nt < 4; nt++)
#pragma unroll
                for (int r = 0; r < 4; r++) Cf[t][nt][r] = 0.f;

#pragma unroll 1
        for (int kc = 0; kc < 8; kc++) {
            CP_WAIT2();
            __syncthreads();
            if (gi + 3 < 32) issue_load(gi + 3);
            CP_COMMIT();

            const float* hb = hbuf + (gi & 3) * HBUF;
#pragma unroll
            for (int ks = 0; ks < 2; ks++) {
                const int s = kc * 2 + ks;
                u32 ahi[2][4], alo[2][4];
#pragma unroll
                for (int t = 0; t < 2; t++) {
                    uint4 h4 = *(const uint4*)(Whi + ((t * 16 + s) * 32 + l) * 4);
                    uint4 l4 = *(const uint4*)(Wlo + ((t * 16 + s) * 32 + l) * 4);
                    ahi[t][0] = h4.x; ahi[t][1] = h4.y; ahi[t][2] = h4.z; ahi[t][3] = h4.w;
                    alo[t][0] = l4.x; alo[t][1] = l4.y; alo[t][2] = l4.z; alo[t][3] = l4.w;
                }
                u32 bhi[4][2], blo[4][2];
                const int rb = (16 * ks + (l & 3) * 2) * HROW + (l >> 2);
#pragma unroll
                for (int nt = 0; nt < 4; nt++) {
                    const int idx = rb + w * 32 + nt * 8;
                    float f00 = hb[idx];
                    float f01 = hb[idx + HROW];
                    float f10 = hb[idx + 8 * HROW];
                    float f11 = hb[idx + 9 * HROW];
                    u32 v00 = __float_as_uint(f00), v01 = __float_as_uint(f01);
                    u32 v10 = __float_as_uint(f10), v11 = __float_as_uint(f11);
                    bhi[nt][0] = prmt_hi(v00, v01);
                    bhi[nt][1] = prmt_hi(v10, v11);
                    float l00 = f00 - maskhi(v00), l01 = f01 - maskhi(v01);
                    float l10 = f10 - maskhi(v10), l11 = f11 - maskhi(v11);
                    blo[nt][0] = cvt_bf2(l01, l00);
                    blo[nt][1] = cvt_bf2(l11, l10);
                }
#pragma unroll
                for (int t = 0; t < 2; t++)
#pragma unroll
                    for (int nt = 0; nt < 4; nt++) {
                        mma_bf16(Cf[t][nt], ahi[t], bhi[nt]);
                        mma_bf16(Cf[t][nt], ahi[t], blo[nt]);
                        mma_bf16(Cf[t][nt], alo[t], bhi[nt]);
                    }
            }
            gi++;
        }

        float* ob = (float*)g_hacc;
        const int lr  = l >> 2;
        const int pxo = 2 * (l & 3);
        const size_t pbase = (size_t)n * HWV + hw0;
#pragma unroll
        for (int t = 0; t < 2; t++)
#pragma unroll
            for (int nt = 0; nt < 4; nt++) {
                const int px = w * 32 + nt * 8 + pxo;
                const int row0 = 16 * t + lr;
                if (row0 < 22) {
                    float2 v; v.x = Cf[t][nt][0]; v.y = Cf[t][nt][1];
                    *(float2*)(ob + (size_t)row0 * NPIX + pbase + px) = v;
                }
                const int row1 = 16 * t + lr + 8;
                if (row1 < 22) {
                    float2 v; v.x = Cf[t][nt][2]; v.y = Cf[t][nt][3];
                    *(float2*)(ob + (size_t)row1 * NPIX + pbase + px) = v;
                }
            }
    }
}

// ============================================================================
// Kernel 2 (scalar, 1 pixel/thread): HID=10 graph ops.
// 24 warps/SM target via __launch_bounds__(128, 6).
// ============================================================================

struct P27 {
    const float* a[27];
    float* out;
};

#define K2T 128

__device__ __forceinline__ float sigm(float x) {
    return __fdividef(1.f, 1.f + __expf(-x));
}

// sw offsets (floats):
// 0: pdp_w1 tail [o*20+k] (400) | 400: pdp_w2 (200) | 600: att_w(20) 620: att_b(2)
// 622: cua(40) 662: cuab(4) 666: cu(200) | 866: cla(20) 886: clab(2) 888: cl(200)
// 1088: dua tail(20) 1108: duab(1) | 1110: du(100)
// 1210: dla tail(20) 1230: dlab(1) | 1232: dl(100)
// 1332: ugu(200) 1532: ugub(10) 1542: ucu(200)
// 1742: ugl(200) 1942: uglb(10) 1952: ucl(200)   total 2152

__global__ void __launch_bounds__(K2T, 6) k2_kernel(P27 p) {
    const float* g_xhu  = p.a[1];
    const float* g_xhl  = p.a[2];
    const float* g_xf   = p.a[3];
    const float* g_xp   = p.a[4];
    const float* w_pdp1 = p.a[5];
    const float* w_pdp2 = p.a[6];
    const float* w_att  = p.a[7];
    const float* b_att  = p.a[8];
    const float* w_cua  = p.a[9];
    const float* b_cua  = p.a[10];
    const float* w_cu   = p.a[11];
    const float* w_cla  = p.a[12];
    const float* b_cla  = p.a[13];
    const float* w_cl   = p.a[14];
    const float* w_dua  = p.a[15];
    const float* b_dua  = p.a[16];
    const float* w_du   = p.a[17];
    const float* w_dla  = p.a[18];
    const float* b_dla  = p.a[19];
    const float* w_dl   = p.a[20];
    const float* w_ugu  = p.a[21];
    const float* b_ugu  = p.a[22];
    const float* w_ucu  = p.a[23];
    const float* w_ugl  = p.a[24];
    const float* b_ugl  = p.a[25];
    const float* w_ucl  = p.a[26];
    float* out = p.out;

    __shared__ float sw[2152];
    __shared__ float sdpu[K2T * 11];

    const int tid = threadIdx.x;
    {
        for (int i = tid; i < 400; i += K2T) { int o = i / 20, k = i % 20; sw[i] = w_pdp1[o * 276 + 256 + k]; }
        for (int i = tid; i < 200; i += K2T) sw[400 + i] = w_pdp2[i];
        for (int i = tid; i < 22;  i += K2T) sw[600 + i] = (i < 20) ? w_att[i] : b_att[i - 20];
        for (int i = tid; i < 44;  i += K2T) sw[622 + i] = (i < 40) ? w_cua[i] : b_cua[i - 40];
        for (int i = tid; i < 200; i += K2T) sw[666 + i] = w_cu[i];
        for (int i = tid; i < 22;  i += K2T) sw[866 + i] = (i < 20) ? w_cla[i] : b_cla[i - 20];
        for (int i = tid; i < 200; i += K2T) sw[888 + i] = w_cl[i];
        for (int i = tid; i < 21;  i += K2T) sw[1088 + i] = (i < 20) ? w_dua[256 + i] : b_dua[0];
        for (int i = tid; i < 100; i += K2T) sw[1110 + i] = w_du[i];
        for (int i = tid; i < 21;  i += K2T) sw[1210 + i] = (i < 20) ? w_dla[256 + i] : b_dla[0];
        for (int i = tid; i < 100; i += K2T) sw[1232 + i] = w_dl[i];
        for (int i = tid; i < 210; i += K2T) sw[1332 + i] = (i < 200) ? w_ugu[i] : b_ugu[i - 200];
        for (int i = tid; i < 200; i += K2T) sw[1542 + i] = w_ucu[i];
        for (int i = tid; i < 210; i += K2T) sw[1742 + i] = (i < 200) ? w_ugl[i] : b_ugl[i - 200];
        for (int i = tid; i < 200; i += K2T) sw[1952 + i] = w_ucl[i];
    }
    __syncthreads();

    const int pix = blockIdx.x * K2T + tid;
    const int n   = pix >> 14;
    const int hw  = pix & (HWV - 1);
    const size_t vb = (size_t)n * HIDN * HWV + hw;
    const float* hac = (const float*)g_hacc + pix;

    float xu[10], xl[10];
#pragma unroll
    for (int i = 0; i < 10; i++) {
        xu[i] = g_xhu[vb + (size_t)i * HWV];
        xl[i] = g_xhl[vb + (size_t)i * HWV];
    }

    // ---- pdp: tt then dp; dpu stashed to smem ----
    float dpl[10];
    {
        float tt[20];
#pragma unroll
        for (int o = 0; o < 20; o++) {
            float a0 = hac[(size_t)o * NPIX], a1 = 0.f;
#pragma unroll
            for (int k = 0; k < 10; k += 2) {
                a0 = fmaf(xu[k],     sw[o * 20 + k],     a0);
                a1 = fmaf(xu[k + 1], sw[o * 20 + k + 1], a1);
            }
#pragma unroll
            for (int k = 0; k < 10; k += 2) {
                a0 = fmaf(xl[k],     sw[o * 20 + 10 + k], a0);
                a1 = fmaf(xl[k + 1], sw[o * 20 + 11 + k], a1);
            }
            tt[o] = fmaxf(a0 + a1, 0.f);
        }
#pragma unroll
        for (int o = 0; o < 10; o++) {
            float a0 = 0.f, a1 = 0.f, b0 = 0.f, b1 = 0.f;
#pragma unroll
            for (int i = 0; i < 10; i += 2) {
                a0 = fmaf(tt[i],      sw[400 + o * 10 + i],     a0);
                a1 = fmaf(tt[i + 1],  sw[400 + o * 10 + i + 1], a1);
                b0 = fmaf(tt[10 + i], sw[500 + o * 10 + i],     b0);
                b1 = fmaf(tt[11 + i], sw[500 + o * 10 + i + 1], b1);
            }
            sdpu[tid * 11 + o] = fmaxf(a0 + a1, 0.f);
            dpl[o] = fmaxf(b0 + b1, 0.f);
        }
    }
    float agu, agl;
    {
        float a = sw[620], b = sw[621];
#pragma unroll
        for (int i = 0; i < 10; i++) {
            a = fmaf(xu[i], sw[600 + i], a);
            b = fmaf(xl[i], sw[610 + i], b);
        }
        agu = sigm(a);
        agl = sigm(b);
    }

    float xf[10];
#pragma unroll
    for (int i = 0; i < 10; i++) xf[i] = g_xf[vb + (size_t)i * HWV];

    // ================= U half =================
    {
        float msg[10];
#pragma unroll
        for (int i = 0; i < 10; i++) msg[i] = 0.f;
#pragma unroll
        for (int pp = 0; pp < 4; pp++) {
            float xv[10];
            const float* xpp = g_xp + ((size_t)(pp * NIMG + n) * HIDN) * HWV + hw;
#pragma unroll
            for (int i = 0; i < 10; i++) xv[i] = xpp[(size_t)i * HWV];
            float s0 = sw[662 + pp], s1 = 0.f;
#pragma unroll
            for (int i = 0; i < 10; i += 2) {
                s0 = fmaf(xv[i],     sw[622 + pp * 10 + i],     s0);
                s1 = fmaf(xv[i + 1], sw[622 + pp * 10 + i + 1], s1);
            }
            float ca = sigm(s0 + s1);
#pragma unroll
            for (int i = 0; i < 10; i++) msg[i] = fmaf(xv[i], ca, msg[i]);
        }
        float m[10];
#pragma unroll
        for (int o = 0; o < 10; o++) {
            float a0 = 0.f, a1 = 0.f;
#pragma unroll
            for (int i = 0; i < 10; i += 2) {
                a0 = fmaf(xu[i],      sw[666 + o * 20 + i],      a0);
                a1 = fmaf(xu[i + 1],  sw[666 + o * 20 + i + 1],  a1);
                a0 = fmaf(msg[i],     sw[666 + o * 20 + 10 + i], a0);
                a1 = fmaf(msg[i + 1], sw[666 + o * 20 + 11 + i], a1);
            }
            float v = fmaxf(a0 + a1, 0.f);     // xphu
            v = fmaf(dpl[o], agl, v);          // + dp_l*ag_l
            m[o] = fmaf(xu[o], agu, v);        // + xh_u*ag_u
        }
        float attu;
        {
            float s0 = hac[(size_t)20 * NPIX] + sw[1108], s1 = 0.f;
#pragma unroll
            for (int i = 0; i < 10; i += 2) {
                s0 = fmaf(xf[i],     sw[1088 + i],     s0);
                s1 = fmaf(xf[i + 1], sw[1088 + i + 1], s1);
                s0 = fmaf(xu[i],     sw[1098 + i],     s0);
                s1 = fmaf(xu[i + 1], sw[1098 + i + 1], s1);
            }
            attu = sigm(s0 + s1);
        }
        out[OUT_ATTU + (size_t)n * HWV + hw] = attu;
        {
            float xfa[10];
#pragma unroll
            for (int i = 0; i < 10; i++) xfa[i] = xf[i] * attu;
#pragma unroll
            for (int o = 0; o < 10; o++) {
                float a0 = 0.f, a1 = 0.f;
#pragma unroll
                for (int i = 0; i < 10; i += 2) {
                    a0 = fmaf(xfa[i],     sw[1110 + o * 10 + i],     a0);
                    a1 = fmaf(xfa[i + 1], sw[1110 + o * 10 + i + 1], a1);
                }
                m[o] += fmaxf(a0 + a1, 0.f);   // + xfhu
            }
        }
#pragma unroll
        for (int o = 0; o < 10; o++) {
            float g0 = sw[1532 + o], g1 = 0.f, c0 = 0.f, c1 = 0.f;
#pragma unroll
            for (int i = 0; i < 10; i += 2) {
                g0 = fmaf(xu[i],     sw[1332 + o * 20 + i],     g0);
                g1 = fmaf(xu[i + 1], sw[1332 + o * 20 + i + 1], g1);
                c0 = fmaf(xu[i],     sw[1542 + o * 20 + i],     c0);
                c1 = fmaf(xu[i + 1], sw[1542 + o * 20 + i + 1], c1);
            }
#pragma unroll
            for (int i = 0; i < 10; i += 2) {
                g0 = fmaf(m[i],     sw[1332 + o * 20 + 10 + i], g0);
                g1 = fmaf(m[i + 1], sw[1332 + o * 20 + 11 + i], g1);
                c0 = fmaf(m[i],     sw[1542 + o * 20 + 10 + i], c0);
                c1 = fmaf(m[i + 1], sw[1542 + o * 20 + 11 + i], c1);
            }
            float g  = sigm(g0 + g1);
            float cd = fmaxf(c0 + c1, 0.f);
            out[(size_t)(n * HIDN + o) * HWV + hw] = fmaf(g, cd - xu[o], xu[o]);
        }
    }

    // ================= L half =================
    {
        float xlv[10], xf2[10];
#pragma unroll
        for (int i = 0; i < 10; i++) {
            xlv[i] = g_xhl[vb + (size_t)i * HWV];
            xf2[i] = g_xf [vb + (size_t)i * HWV];
        }
        float msg[10];
#pragma unroll
        for (int i = 0; i < 10; i++) msg[i] = 0.f;
#pragma unroll
        for (int pp = 0; pp < 2; pp++) {
            float xv[10];
            const float* xpp = g_xp + ((size_t)((4 + pp) * NIMG + n) * HIDN) * HWV + hw;
#pragma unroll
            for (int i = 0; i < 10; i++) xv[i] = xpp[(size_t)i * HWV];
            float s0 = sw[886 + pp], s1 = 0.f;
#pragma unroll
            for (int i = 0; i < 10; i += 2) {
                s0 = fmaf(xv[i],     sw[866 + pp * 10 + i],     s0);
                s1 = fmaf(xv[i + 1], sw[866 + pp * 10 + i + 1], s1);
            }
            float ca = sigm(s0 + s1);
#pragma unroll
            for (int i = 0; i < 10; i++) msg[i] = fmaf(xv[i], ca, msg[i]);
        }
        float m[10];
#pragma unroll
        for (int o = 0; o < 10; o++) {
            float a0 = 0.f, a1 = 0.f;
#pragma unroll
            for (int i = 0; i < 10; i += 2) {
                a0 = fmaf(xlv[i],     sw[888 + o * 20 + i],      a0);
                a1 = fmaf(xlv[i + 1], sw[888 + o * 20 + i + 1],  a1);
                a0 = fmaf(msg[i],     sw[888 + o * 20 + 10 + i], a0);
                a1 = fmaf(msg[i + 1], sw[888 + o * 20 + 11 + i], a1);
            }
            float v = fmaxf(a0 + a1, 0.f);           // xphl
            v = fmaf(sdpu[tid * 11 + o], agu, v);    // + dp_u*ag_u
            m[o] = fmaf(xlv[o], agl, v);             // + xh_l*ag_l
        }
        float attl;
        {
            float s0 = hac[(size_t)21 * NPIX] + sw[1230], s1 = 0.f;
#pragma unroll
            for (int i = 0; i < 10; i += 2) {
                s0 = fmaf(xf2[i],     sw[1210 + i],     s0);
                s1 = fmaf(xf2[i + 1], sw[1210 + i + 1], s1);
                s0 = fmaf(xlv[i],     sw[1220 + i],     s0);
                s1 = fmaf(xlv[i + 1], sw[1220 + i + 1], s1);
            }
            attl = sigm(s0 + s1);
        }
        out[OUT_ATTL + (size_t)n * HWV + hw] = attl;
        {
            float xfa[10];
#pragma unroll
            for (int i = 0; i < 10; i++) xfa[i] = xf2[i] * attl;
#pragma unroll
            for (int o = 0; o < 10; o++) {
                float a0 = 0.f, a1 = 0.f;
#pragma unroll
                for (int i = 0; i < 10; i += 2) {
                    a0 = fmaf(xfa[i],     sw[1232 + o * 10 + i],     a0);
                    a1 = fmaf(xfa[i + 1], sw[1232 + o * 10 + i + 1], a1);
                }
                m[o] += fmaxf(a0 + a1, 0.f);   // + xfhl
            }
        }
#pragma unroll
        for (int o = 0; o < 10; o++) {
            float g0 = sw[1942 + o], g1 = 0.f, c0 = 0.f, c1 = 0.f;
#pragma unroll
            for (int i = 0; i < 10; i += 2) {
                g0 = fmaf(xlv[i],     sw[1742 + o * 20 + i],     g0);
                g1 = fmaf(xlv[i + 1], sw[1742 + o * 20 + i + 1], g1);
                c0 = fmaf(xlv[i],     sw[1952 + o * 20 + i],     c0);
                c1 = fmaf(xlv[i + 1], sw[1952 + o * 20 + i + 1], c1);
            }
#pragma unroll
            for (int i = 0; i < 10; i += 2) {
                g0 = fmaf(m[i],     sw[1742 + o * 20 + 10 + i], g0);
                g1 = fmaf(m[i + 1], sw[1742 + o * 20 + 11 + i], g1);
                c0 = fmaf(m[i],     sw[1952 + o * 20 + 10 + i], c0);
                c1 = fmaf(m[i + 1], sw[1952 + o * 20 + 11 + i], c1);
            }
            float g  = sigm(g0 + g1);
            float cd = fmaxf(c0 + c1, 0.f);
            out[OUT_XHL + (size_t)(n * HIDN + o) * HWV + hw] = fmaf(g, cd - xlv[o], xlv[o]);
        }
    }
}

extern "C" void kernel_launch(void* const* d_in, const int* in_sizes, int n_in,
                              void* d_out, int out_size) {
    cudaFuncSetAttribute(k1t_kernel, cudaFuncAttributeMaxDynamicSharedMemorySize,
                         K1_SMEM_BYTES);
    k1t_kernel<<<128, 256, K1_SMEM_BYTES>>>((const float*)d_in[0], (const float*)d_in[5],
                                            (const float*)d_in[15], (const float*)d_in[18]);
    P27 p;
    for (int i = 0; i < 27; i++) p.a[i] = (const float*)d_in[i];
    p.out = (float*)d_out;
    k2_kernel<<<1024, K2T>>>(p);
}

// round 15
// speedup vs baseline: 1.0785x; 1.0785x over previous
#include <cuda_runtime.h>
#include <cuda_bf16.h>

typedef unsigned long long u64;
typedef unsigned int u32;

#define HIDN 10
#define CCH  256
#define HWV  16384
#define NIMG 8
#define NPAIR 65536
#define NPIX 131072
// output offsets (floats)
#define OUT_XHL  1310720
#define OUT_ATTU 2621440
#define OUT_ATTL 2752512

// scratch: 22 planes of dots; float view [22][131072]
__device__ __align__(16) u64 g_hacc[22 * NPAIR];

// ---------- packed f32x2 helpers (k2) ----------
__device__ __forceinline__ u64 ffma2(u64 a, u64 b, u64 c) {
    u64 d; asm("fma.rn.f32x2 %0,%1,%2,%3;" : "=l"(d) : "l"(a), "l"(b), "l"(c)); return d;
}
__device__ __forceinline__ u64 fmul2(u64 a, u64 b) {
    u64 d; asm("mul.rn.f32x2 %0,%1,%2;" : "=l"(d) : "l"(a), "l"(b)); return d;
}
__device__ __forceinline__ u64 fadd2(u64 a, u64 b) {
    u64 d; asm("add.rn.f32x2 %0,%1,%2;" : "=l"(d) : "l"(a), "l"(b)); return d;
}
__device__ __forceinline__ u64 pack2(float x, float y) {
    u64 d; asm("mov.b64 %0,{%1,%2};" : "=l"(d) : "f"(x), "f"(y)); return d;
}
__device__ __forceinline__ void unpack2(u64 a, float& x, float& y) {
    asm("mov.b64 {%0,%1},%2;" : "=f"(x), "=f"(y) : "l"(a));
}
__device__ __forceinline__ u64 dup2(float x) { return pack2(x, x); }
__device__ __forceinline__ u64 relu2(u64 a) {
    float x, y; unpack2(a, x, y);
    return pack2(fmaxf(x, 0.f), fmaxf(y, 0.f));
}
__device__ __forceinline__ u64 sigmoid2(u64 a) {
    float x, y; unpack2(a, x, y);
    x = __fdividef(1.f, 1.f + __expf(-x));
    y = __fdividef(1.f, 1.f + __expf(-y));
    return pack2(x, y);
}
__device__ __forceinline__ u64 neg2(u64 a) { return a ^ 0x8000000080000000ULL; }

struct uu2 { u64 x, y; };
__device__ __forceinline__ uu2 lds2(const u64* p) {
    uu2 r;
    asm("ld.shared.v2.u64 {%0,%1}, [%2];" : "=l"(r.x), "=l"(r.y) : "l"(__cvta_generic_to_shared(p)));
    return r;
}

// ---------- bf16 split / mma helpers (k1) ----------
__device__ __forceinline__ u32 bfb(float f) {
    return (u32)__bfloat16_as_ushort(__float2bfloat16(f));
}
__device__ __forceinline__ float bff(u32 u) {
    return __bfloat162float(__ushort_as_bfloat16((unsigned short)u));
}
__device__ __forceinline__ u32 prmt_hi(u32 a, u32 b) {
    u32 d; asm("prmt.b32 %0,%1,%2,0x7632;" : "=r"(d) : "r"(a), "r"(b)); return d;
}
__device__ __forceinline__ u32 cvt_bf2(float hi, float lo) {
    u32 d; asm("cvt.rn.bf16x2.f32 %0,%1,%2;" : "=r"(d) : "f"(hi), "f"(lo)); return d;
}
__device__ __forceinline__ float maskhi(u32 v) {
    return __uint_as_float(v & 0xFFFF0000u);
}
__device__ __forceinline__ void mma_bf16(float (&d)[4], const u32 (&a)[4], const u32* b) {
    asm volatile(
        "mma.sync.aligned.m16n8k16.row.col.f32.bf16.bf16.f32 "
        "{%0,%1,%2,%3},{%4,%5,%6,%7},{%8,%9},{%0,%1,%2,%3};"
        : "+f"(d[0]), "+f"(d[1]), "+f"(d[2]), "+f"(d[3])
        : "r"(a[0]), "r"(a[1]), "r"(a[2]), "r"(a[3]), "r"(b[0]), "r"(b[1]));
}
__device__ __forceinline__ void cp16(float* dst, const float* src) {
    u32 ds = (u32)__cvta_generic_to_shared(dst);
    asm volatile("cp.async.cg.shared.global [%0], [%1], 16;" :: "r"(ds), "l"(src));
}
#define CP_COMMIT()  asm volatile("cp.async.commit_group;" ::: "memory")
#define CP_WAIT0()   asm volatile("cp.async.wait_group 0;" ::: "memory")

// ============================================================================
// Kernel 1 (tensor): hacc[22][pix] = W[22x256] . hfea[256][pix]
// bf16 hi/lo split (3 products, m16n8k16). Grid 512, one 256-px chunk per
// block, 2-stage ring, 2 blocks/SM (16 warps/SM) — occupancy experiment.
// ============================================================================

#define HROW 264
#define HBUF (32 * HROW)
#define K1_SMEM_BYTES ((8192 + 2 * HBUF) * 4)

__global__ void __launch_bounds__(256, 2) k1t_kernel(const float* __restrict__ hfea,
                                                     const float* __restrict__ w_pdp1,
                                                     const float* __restrict__ w_dua,
                                                     const float* __restrict__ w_dla) {
    extern __shared__ u32 smemu[];
    u32*   Whi  = smemu;              // [2 mtile][16 ks16][32 lane][4] = 4096
    u32*   Wlo  = smemu + 4096;       // 4096
    float* hbuf = (float*)(smemu + 8192);  // 2 x HBUF floats

    const int tid = threadIdx.x;
    const int w   = tid >> 5;
    const int l   = tid & 31;
    const int bid = blockIdx.x;       // chunk id, 0..511
    const int n   = bid >> 6;
    const int hw0 = (bid & 63) << 8;

    // ---- weight prep: bf16 hi/lo, pre-swizzled into m16n8k16 A-frag order ----
    for (int sidx = tid; sidx < 1024; sidx += 256) {
        int t = sidx >> 9, rem = sidx & 511, s = rem >> 5, ln = rem & 31;
#pragma unroll
        for (int r = 0; r < 4; r++) {
            int row = 16 * t + (ln >> 2) + 8 * (r & 1);
            int k0  = 16 * s + (ln & 3) * 2 + 8 * (r >> 1);
            float v0 = 0.f, v1 = 0.f;
            if (row < 20)       { v0 = w_pdp1[row * 276 + k0]; v1 = w_pdp1[row * 276 + k0 + 1]; }
            else if (row == 20) { v0 = w_dua[k0]; v1 = w_dua[k0 + 1]; }
            else if (row == 21) { v0 = w_dla[k0]; v1 = w_dla[k0 + 1]; }
            u32 h0 = bfb(v0), h1 = bfb(v1);
            Whi[sidx * 4 + r] = (h1 << 16) | h0;
            float lo0 = v0 - bff(h0), lo1 = v1 - bff(h1);
            Wlo[sidx * 4 + r] = (bfb(lo1) << 16) | bfb(lo0);
        }
    }

    const int row  = tid >> 3;        // 0..31 (channel within tile)
    const int seg0 = tid & 7;
    auto issue_load = [&](int kk) {   // kk = 0..7, stage kk&1
        const float* srcr = hfea + ((size_t)(n * CCH + kk * 32) + row) * HWV + hw0;
        float* dstr = hbuf + (kk & 1) * HBUF + row * HROW;
#pragma unroll
        for (int j = 0; j < 8; j++) { int seg = seg0 + j * 8; cp16(dstr + seg * 4, srcr + seg * 4); }
    };

    issue_load(0);
    CP_COMMIT();

    float Cf[2][4][4];
#pragma unroll
    for (int t = 0; t < 2; t++)
#pragma unroll
        for (int nt = 0; nt < 4; nt++)
#pragma unroll
            for (int r = 0; r < 4; r++) Cf[t][nt][r] = 0.f;

#pragma unroll 1
    for (int kc = 0; kc < 8; kc++) {
        CP_WAIT0();          // load kc (the only outstanding group) done
        __syncthreads();     // data visible; all warps done with stage (kc+1)&1
        if (kc < 7) { issue_load(kc + 1); CP_COMMIT(); }

        const float* hb = hbuf + (kc & 1) * HBUF;
#pragma unroll
        for (int ks = 0; ks < 2; ks++) {
            const int s = kc * 2 + ks;
            u32 ahi[2][4], alo[2][4];
#pragma unroll
            for (int t = 0; t < 2; t++) {
                uint4 h4 = *(const uint4*)(Whi + ((t * 16 + s) * 32 + l) * 4);
                uint4 l4 = *(const uint4*)(Wlo + ((t * 16 + s) * 32 + l) * 4);
                ahi[t][0] = h4.x; ahi[t][1] = h4.y; ahi[t][2] = h4.z; ahi[t][3] = h4.w;
                alo[t][0] = l4.x; alo[t][1] = l4.y; alo[t][2] = l4.z; alo[t][3] = l4.w;
            }
            u32 bhi[4][2], blo[4][2];
            const int rb = (16 * ks + (l & 3) * 2) * HROW + (l >> 2);
#pragma unroll
            for (int nt = 0; nt < 4; nt++) {
                const int idx = rb + w * 32 + nt * 8;
                float f00 = hb[idx];
                float f01 = hb[idx + HROW];
                float f10 = hb[idx + 8 * HROW];
                float f11 = hb[idx + 9 * HROW];
                u32 v00 = __float_as_uint(f00), v01 = __float_as_uint(f01);
                u32 v10 = __float_as_uint(f10), v11 = __float_as_uint(f11);
                bhi[nt][0] = prmt_hi(v00, v01);
                bhi[nt][1] = prmt_hi(v10, v11);
                float l00 = f00 - maskhi(v00), l01 = f01 - maskhi(v01);
                float l10 = f10 - maskhi(v10), l11 = f11 - maskhi(v11);
                blo[nt][0] = cvt_bf2(l01, l00);
                blo[nt][1] = cvt_bf2(l11, l10);
            }
#pragma unroll
            for (int t = 0; t < 2; t++)
#pragma unroll
                for (int nt = 0; nt < 4; nt++) {
                    mma_bf16(Cf[t][nt], ahi[t], bhi[nt]);
                    mma_bf16(Cf[t][nt], ahi[t], blo[nt]);
                    mma_bf16(Cf[t][nt], alo[t], bhi[nt]);
                }
        }
        __syncthreads();     // stage kc&1 fully consumed before iter kc+2 reloads it
    }

    // ---- store: rows 0..21, float2 per lane ----
    float* ob = (float*)g_hacc;
    const int lr  = l >> 2;
    const int pxo = 2 * (l & 3);
    const size_t pbase = (size_t)n * HWV + hw0;
#pragma unroll
    for (int t = 0; t < 2; t++)
#pragma unroll
        for (int nt = 0; nt < 4; nt++) {
            const int px = w * 32 + nt * 8 + pxo;
            const int row0 = 16 * t + lr;
            if (row0 < 22) {
                float2 v; v.x = Cf[t][nt][0]; v.y = Cf[t][nt][1];
                *(float2*)(ob + (size_t)row0 * NPIX + pbase + px) = v;
            }
            const int row1 = 16 * t + lr + 8;
            if (row1 < 22) {
                float2 v; v.x = Cf[t][nt][2]; v.y = Cf[t][nt][3];
                *(float2*)(ob + (size_t)row1 * NPIX + pbase + px) = v;
            }
        }
}

// ============================================================================
// Kernel 2: HID=10 graph ops, packed over the pixel pair (R12 version).
// ============================================================================

struct P27 {
    const float* a[27];
    float* out;
};

#define K2T 128

__global__ void __launch_bounds__(K2T, 4) k2_kernel(P27 p) {
    const float* g_xhu  = p.a[1];
    const float* g_xhl  = p.a[2];
    const float* g_xf   = p.a[3];
    const float* g_xp   = p.a[4];
    const float* w_pdp1 = p.a[5];
    const float* w_pdp2 = p.a[6];
    const float* w_att  = p.a[7];
    const float* b_att  = p.a[8];
    const float* w_cua  = p.a[9];
    const float* b_cua  = p.a[10];
    const float* w_cu   = p.a[11];
    const float* w_cla  = p.a[12];
    const float* b_cla  = p.a[13];
    const float* w_cl   = p.a[14];
    const float* w_dua  = p.a[15];
    const float* b_dua  = p.a[16];
    const float* w_du   = p.a[17];
    const float* w_dla  = p.a[18];
    const float* b_dla  = p.a[19];
    const float* w_dl   = p.a[20];
    const float* w_ugu  = p.a[21];
    const float* b_ugu  = p.a[22];
    const float* w_ucu  = p.a[23];
    const float* w_ugl  = p.a[24];
    const float* b_ugl  = p.a[25];
    const float* w_ucl  = p.a[26];
    float* out = p.out;

    __shared__ __align__(16) u64 s_small[2152];
    __shared__ u64 s_dpu[K2T * 11];

    const int tid = threadIdx.x;
    {
        for (int i = tid; i < 400; i += K2T) { int o = i / 20, k = i % 20; s_small[i] = dup2(w_pdp1[o * 276 + 256 + k]); }
        for (int i = tid; i < 200; i += K2T) s_small[400 + i] = dup2(w_pdp2[i]);
        for (int i = tid; i < 22;  i += K2T) s_small[600 + i] = (i < 20) ? dup2(w_att[i]) : dup2(b_att[i - 20]);
        for (int i = tid; i < 44;  i += K2T) s_small[622 + i] = (i < 40) ? dup2(w_cua[i]) : dup2(b_cua[i - 40]);
        for (int i = tid; i < 200; i += K2T) s_small[666 + i] = dup2(w_cu[i]);
        for (int i = tid; i < 22;  i += K2T) s_small[866 + i] = (i < 20) ? dup2(w_cla[i]) : dup2(b_cla[i - 20]);
        for (int i = tid; i < 200; i += K2T) s_small[888 + i] = dup2(w_cl[i]);
        for (int i = tid; i < 21;  i += K2T) s_small[1088 + i] = (i < 20) ? dup2(w_dua[256 + i]) : dup2(b_dua[0]);
        for (int i = tid; i < 100; i += K2T) s_small[1110 + i] = dup2(w_du[i]);
        for (int i = tid; i < 21;  i += K2T) s_small[1210 + i] = (i < 20) ? dup2(w_dla[256 + i]) : dup2(b_dla[0]);
        for (int i = tid; i < 100; i += K2T) s_small[1232 + i] = dup2(w_dl[i]);
        for (int i = tid; i < 210; i += K2T) s_small[1332 + i] = (i < 200) ? dup2(w_ugu[i]) : dup2(b_ugu[i - 200]);
        for (int i = tid; i < 200; i += K2T) s_small[1542 + i] = dup2(w_ucu[i]);
        for (int i = tid; i < 210; i += K2T) s_small[1742 + i] = (i < 200) ? dup2(w_ugl[i]) : dup2(b_ugl[i - 200]);
        for (int i = tid; i < 200; i += K2T) s_small[1952 + i] = dup2(w_ucl[i]);
    }
    __syncthreads();

    const int pair = blockIdx.x * K2T + tid;
    const int pix  = pair * 2;
    const int n    = pix >> 14;
    const int hw   = pix & (HWV - 1);
    const size_t vb = (size_t)n * HIDN * HWV + hw;
    const u64* hac = g_hacc + pair;

    u64 xu[10], xl[10];
#pragma unroll
    for (int i = 0; i < 10; i++) {
        xu[i] = *(const u64*)(g_xhu + vb + (size_t)i * HWV);
        xl[i] = *(const u64*)(g_xhl + vb + (size_t)i * HWV);
    }

    u64 dpl[10];
    {
        u64 tt[20];
#pragma unroll
        for (int o = 0; o < 20; o++) {
            u64 a = hac[(size_t)o * NPAIR];
            const u64* wr = s_small + o * 20;
#pragma unroll
            for (int k = 0; k < 10; k += 2) {
                uu2 w = lds2(wr + k);
                a = ffma2(xu[k], w.x, a);
                a = ffma2(xu[k + 1], w.y, a);
            }
#pragma unroll
            for (int k = 0; k < 10; k += 2) {
                uu2 w = lds2(wr + 10 + k);
                a = ffma2(xl[k], w.x, a);
                a = ffma2(xl[k + 1], w.y, a);
            }
            tt[o] = relu2(a);
        }
#pragma unroll
        for (int o = 0; o < 10; o++) {
            u64 a = 0ULL, b = 0ULL;
#pragma unroll
            for (int i = 0; i < 10; i += 2) {
                uu2 wa = lds2(s_small + 400 + o * 10 + i);
                uu2 wb = lds2(s_small + 500 + o * 10 + i);
                a = ffma2(tt[i],      wa.x, a);
                a = ffma2(tt[i + 1],  wa.y, a);
                b = ffma2(tt[10 + i], wb.x, b);
                b = ffma2(tt[11 + i], wb.y, b);
            }
            s_dpu[tid * 11 + o] = relu2(a);
            dpl[o] = relu2(b);
        }
    }
    u64 agu, agl;
    {
        u64 a = s_small[620], b = s_small[621];
#pragma unroll
        for (int i = 0; i < 10; i += 2) {
            uu2 wa = lds2(s_small + 600 + i);
            uu2 wb = lds2(s_small + 610 + i);
            a = ffma2(xu[i], wa.x, a);
            a = ffma2(xu[i + 1], wa.y, a);
            b = ffma2(xl[i], wb.x, b);
            b = ffma2(xl[i + 1], wb.y, b);
        }
        agu = sigmoid2(a);
        agl = sigmoid2(b);
    }

    u64 xfv[10];
#pragma unroll
    for (int i = 0; i < 10; i++) xfv[i] = *(const u64*)(g_xf + vb + (size_t)i * HWV);

    // ================= U half =================
    {
        u64 msg[10];
#pragma unroll
        for (int i = 0; i < 10; i++) msg[i] = 0ULL;
#pragma unroll
        for (int pp = 0; pp < 4; pp++) {
            u64 xv[10];
            const float* xpp = g_xp + ((size_t)(pp * NIMG + n) * HIDN) * HWV + hw;
#pragma unroll
            for (int i = 0; i < 10; i++) xv[i] = *(const u64*)(xpp + (size_t)i * HWV);
            u64 s = s_small[662 + pp];
#pragma unroll
            for (int i = 0; i < 10; i += 2) {
                uu2 w = lds2(s_small + 622 + pp * 10 + i);
                s = ffma2(xv[i], w.x, s);
                s = ffma2(xv[i + 1], w.y, s);
            }
            u64 ca = sigmoid2(s);
#pragma unroll
            for (int i = 0; i < 10; i++) msg[i] = ffma2(xv[i], ca, msg[i]);
        }
        u64 m[10];
#pragma unroll
        for (int o = 0; o < 10; o++) {
            u64 a = 0ULL;
            const u64* wr = s_small + 666 + o * 20;
#pragma unroll
            for (int i = 0; i < 10; i += 2) {
                uu2 wa = lds2(wr + i);
                uu2 wb = lds2(wr + 10 + i);
                a = ffma2(xu[i],  wa.x, a);
                a = ffma2(xu[i + 1], wa.y, a);
                a = ffma2(msg[i], wb.x, a);
                a = ffma2(msg[i + 1], wb.y, a);
            }
            m[o] = relu2(a);
            m[o] = ffma2(dpl[o], agl, m[o]);
            m[o] = ffma2(xu[o],  agu, m[o]);
        }
        u64 attu;
        {
            u64 s = fadd2(hac[(size_t)20 * NPAIR], s_small[1108]);
#pragma unroll
            for (int i = 0; i < 10; i += 2) {
                uu2 wa = lds2(s_small + 1088 + i);
                uu2 wb = lds2(s_small + 1098 + i);
                s = ffma2(xfv[i], wa.x, s);
                s = ffma2(xfv[i + 1], wa.y, s);
                s = ffma2(xu[i],  wb.x, s);
                s = ffma2(xu[i + 1], wb.y, s);
            }
            attu = sigmoid2(s);
        }
        *(u64*)(out + OUT_ATTU + (size_t)n * HWV + hw) = attu;
        {
            u64 xfa[10];
#pragma unroll
            for (int i = 0; i < 10; i++) xfa[i] = fmul2(xfv[i], attu);
#pragma unroll
            for (int o = 0; o < 10; o++) {
                u64 a = 0ULL;
#pragma unroll
                for (int i = 0; i < 10; i += 2) {
                    uu2 w = lds2(s_small + 1110 + o * 10 + i);
                    a = ffma2(xfa[i], w.x, a);
                    a = ffma2(xfa[i + 1], w.y, a);
                }
                m[o] = fadd2(m[o], relu2(a));
            }
        }
#pragma unroll
        for (int o = 0; o < 10; o++) {
            u64 g  = s_small[1532 + o];
            u64 cd = 0ULL;
            const u64* wg = s_small + 1332 + o * 20;
            const u64* wc = s_small + 1542 + o * 20;
#pragma unroll
            for (int i = 0; i < 10; i += 2) {
                uu2 a1 = lds2(wg + i);
                uu2 a2 = lds2(wc + i);
                g  = ffma2(xu[i], a1.x, g);
                g  = ffma2(xu[i + 1], a1.y, g);
                cd = ffma2(xu[i], a2.x, cd);
                cd = ffma2(xu[i + 1], a2.y, cd);
            }
#pragma unroll
            for (int i = 0; i < 10; i += 2) {
                uu2 a1 = lds2(wg + 10 + i);
                uu2 a2 = lds2(wc + 10 + i);
                g  = ffma2(m[i], a1.x, g);
                g  = ffma2(m[i + 1], a1.y, g);
                cd = ffma2(m[i], a2.x, cd);
                cd = ffma2(m[i + 1], a2.y, cd);
            }
            g  = sigmoid2(g);
            cd = relu2(cd);
            u64 res = ffma2(g, fadd2(cd, neg2(xu[o])), xu[o]);
            *(u64*)(out + (size_t)(n * HIDN + o) * HWV + hw) = res;
        }
    }

    // ================= L half =================
    {
        u64 xlv[10], xf2[10];
#pragma unroll
        for (int i = 0; i < 10; i++) {
            xlv[i] = *(const u64*)(g_xhl + vb + (size_t)i * HWV);
            xf2[i] = *(const u64*)(g_xf  + vb + (size_t)i * HWV);
        }
        u64 msg[10];
#pragma unroll
        for (int i = 0; i < 10; i++) msg[i] = 0ULL;
#pragma unroll
        for (int pp = 0; pp < 2; pp++) {
            u64 xv[10];
            const float* xpp = g_xp + ((size_t)((4 + pp) * NIMG + n) * HIDN) * HWV + hw;
#pragma unroll
            for (int i = 0; i < 10; i++) xv[i] = *(const u64*)(xpp + (size_t)i * HWV);
            u64 s = s_small[886 + pp];
#pragma unroll
            for (int i = 0; i < 10; i += 2) {
                uu2 w = lds2(s_small + 866 + pp * 10 + i);
                s = ffma2(xv[i], w.x, s);
                s = ffma2(xv[i + 1], w.y, s);
            }
            u64 ca = sigmoid2(s);
#pragma unroll
            for (int i = 0; i < 10; i++) msg[i] = ffma2(xv[i], ca, msg[i]);
        }
        u64 m[10];
#pragma unroll
        for (int o = 0; o < 10; o++) {
            u64 a = 0ULL;
            const u64* wr = s_small + 888 + o * 20;
#pragma unroll
            for (int i = 0; i < 10; i += 2) {
                uu2 wa = lds2(wr + i);
                uu2 wb = lds2(wr + 10 + i);
                a = ffma2(xlv[i], wa.x, a);
                a = ffma2(xlv[i + 1], wa.y, a);
                a = ffma2(msg[i], wb.x, a);
                a = ffma2(msg[i + 1], wb.y, a);
            }
            m[o] = relu2(a);
            m[o] = ffma2(s_dpu[tid * 11 + o], agu, m[o]);
            m[o] = ffma2(xlv[o], agl, m[o]);
        }
        u64 attl;
        {
            u64 s = fadd2(hac[(size_t)21 * NPAIR], s_small[1230]);
#pragma unroll
            for (int i = 0; i < 10; i += 2) {
                uu2 wa = lds2(s_small + 1210 + i);
                uu2 wb = lds2(s_small + 1220 + i);
                s = ffma2(xf2[i], wa.x, s);
                s = ffma2(xf2[i + 1], wa.y, s);
                s = ffma2(xlv[i], wb.x, s);
                s = ffma2(xlv[i + 1], wb.y, s);
            }
            attl = sigmoid2(s);
        }
        *(u64*)(out + OUT_ATTL + (size_t)n * HWV + hw) = attl;
        {
            u64 xfa[10];
#pragma unroll
            for (int i = 0; i < 10; i++) xfa[i] = fmul2(xf2[i], attl);
#pragma unroll
            for (int o = 0; o < 10; o++) {
                u64 a = 0ULL;
#pragma unroll
                for (int i = 0; i < 10; i += 2) {
                    uu2 w = lds2(s_small + 1232 + o * 10 + i);
                    a = ffma2(xfa[i], w.x, a);
                    a = ffma2(xfa[i + 1], w.y, a);
                }
                m[o] = fadd2(m[o], relu2(a));
            }
        }
#pragma unroll
        for (int o = 0; o < 10; o++) {
            u64 g  = s_small[1942 + o];
            u64 cd = 0ULL;
            const u64* wg = s_small + 1742 + o * 20;
            const u64* wc = s_small + 1952 + o * 20;
#pragma unroll
            for (int i = 0; i < 10; i += 2) {
                uu2 a1 = lds2(wg + i);
                uu2 a2 = lds2(wc + i);
                g  = ffma2(xlv[i], a1.x, g);
                g  = ffma2(xlv[i + 1], a1.y, g);
                cd = ffma2(xlv[i], a2.x, cd);
                cd = ffma2(xlv[i + 1], a2.y, cd);
            }
#pragma unroll
            for (int i = 0; i < 10; i += 2) {
                uu2 a1 = lds2(wg + 10 + i);
                uu2 a2 = lds2(wc + 10 + i);
                g  = ffma2(m[i], a1.x, g);
                g  = ffma2(m[i + 1], a1.y, g);
                cd = ffma2(m[i], a2.x, cd);
                cd = ffma2(m[i + 1], a2.y, cd);
            }
            g  = sigmoid2(g);
            cd = relu2(cd);
            u64 res = ffma2(g, fadd2(cd, neg2(xlv[o])), xlv[o]);
            *(u64*)(out + OUT_XHL + (size_t)(n * HIDN + o) * HWV + hw) = res;
        }
    }
}

extern "C" void kernel_launch(void* const* d_in, const int* in_sizes, int n_in,
                              void* d_out, int out_size) {
    cudaFuncSetAttribute(k1t_kernel, cudaFuncAttributeMaxDynamicSharedMemorySize,
                         K1_SMEM_BYTES);
    k1t_kernel<<<512, 256, K1_SMEM_BYTES>>>((const float*)d_in[0], (const float*)d_in[5],
                                            (const float*)d_in[15], (const float*)d_in[18]);
    P27 p;
    for (int i = 0; i < 27; i++) p.a[i] = (const float*)d_in[i];
    p.out = (float*)d_out;
    k2_kernel<<<512, K2T>>>(p);
}

// round 16
// speedup vs baseline: 1.2401x; 1.1499x over previous
#include <cuda_runtime.h>
#include <cuda_fp16.h>

typedef unsigned long long u64;
typedef unsigned int u32;

#define HIDN 10
#define CCH  256
#define HWV  16384
#define NIMG 8
#define NPAIR 65536
#define NPIX 131072
// output offsets (floats)
#define OUT_XHL  1310720
#define OUT_ATTU 2621440
#define OUT_ATTL 2752512

// scratch: 22 planes of dots; float view [22][131072]
__device__ __align__(16) u64 g_hacc[22 * NPAIR];

// ---------- packed f32x2 helpers (k2) ----------
__device__ __forceinline__ u64 ffma2(u64 a, u64 b, u64 c) {
    u64 d; asm("fma.rn.f32x2 %0,%1,%2,%3;" : "=l"(d) : "l"(a), "l"(b), "l"(c)); return d;
}
__device__ __forceinline__ u64 fmul2(u64 a, u64 b) {
    u64 d; asm("mul.rn.f32x2 %0,%1,%2;" : "=l"(d) : "l"(a), "l"(b)); return d;
}
__device__ __forceinline__ u64 fadd2(u64 a, u64 b) {
    u64 d; asm("add.rn.f32x2 %0,%1,%2;" : "=l"(d) : "l"(a), "l"(b)); return d;
}
__device__ __forceinline__ u64 pack2(float x, float y) {
    u64 d; asm("mov.b64 %0,{%1,%2};" : "=l"(d) : "f"(x), "f"(y)); return d;
}
__device__ __forceinline__ void unpack2(u64 a, float& x, float& y) {
    asm("mov.b64 {%0,%1},%2;" : "=f"(x), "=f"(y) : "l"(a));
}
__device__ __forceinline__ u64 dup2(float x) { return pack2(x, x); }
__device__ __forceinline__ u64 relu2(u64 a) {
    float x, y; unpack2(a, x, y);
    return pack2(fmaxf(x, 0.f), fmaxf(y, 0.f));
}
__device__ __forceinline__ u64 sigmoid2(u64 a) {
    float x, y; unpack2(a, x, y);
    x = __fdividef(1.f, 1.f + __expf(-x));
    y = __fdividef(1.f, 1.f + __expf(-y));
    return pack2(x, y);
}
__device__ __forceinline__ u64 neg2(u64 a) { return a ^ 0x8000000080000000ULL; }

struct uu2 { u64 x, y; };
__device__ __forceinline__ uu2 lds2(const u64* p) {
    uu2 r;
    asm("ld.shared.v2.u64 {%0,%1}, [%2];" : "=l"(r.x), "=l"(r.y) : "l"(__cvta_generic_to_shared(p)));
    return r;
}

// ---------- fp16 mma helpers (k1) ----------
__device__ __forceinline__ u32 f16b(float f) {
    return (u32)__half_as_ushort(__float2half_rn(f));
}
// d.lo = lo, d.hi = hi (same arg convention as validated bf16 variant)
__device__ __forceinline__ u32 cvt_f16x2(float hi, float lo) {
    u32 d; asm("cvt.rn.f16x2.f32 %0,%1,%2;" : "=r"(d) : "f"(hi), "f"(lo)); return d;
}
__device__ __forceinline__ void mma_f16(float (&d)[4], const u32 (&a)[4], const u32* b) {
    asm volatile(
        "mma.sync.aligned.m16n8k16.row.col.f32.f16.f16.f32 "
        "{%0,%1,%2,%3},{%4,%5,%6,%7},{%8,%9},{%0,%1,%2,%3};"
        : "+f"(d[0]), "+f"(d[1]), "+f"(d[2]), "+f"(d[3])
        : "r"(a[0]), "r"(a[1]), "r"(a[2]), "r"(a[3]), "r"(b[0]), "r"(b[1]));
}
__device__ __forceinline__ void cp16(float* dst, const float* src) {
    u32 ds = (u32)__cvta_generic_to_shared(dst);
    asm volatile("cp.async.cg.shared.global [%0], [%1], 16;" :: "r"(ds), "l"(src));
}
#define CP_COMMIT() asm volatile("cp.async.commit_group;" ::: "memory")
#define CP_WAIT2()  asm volatile("cp.async.wait_group 2;" ::: "memory")

// ============================================================================
// Kernel 1 (tensor): hacc[22][pix] = W[22x256] . hfea[256][pix]
// Single-product fp16 m16n8k16 (fp32 accum). R12 chassis: persistent 128
// blocks, 256-px chunks, 4-stage cp.async ring, one __syncthreads per k-iter.
// ============================================================================

#define HROW 264
#define HBUF (32 * HROW)
#define K1_STAGES 4
#define K1_SMEM_BYTES ((4096 + K1_STAGES * HBUF) * 4)

__global__ void __launch_bounds__(256) k1t_kernel(const float* __restrict__ hfea,
                                                  const float* __restrict__ w_pdp1,
                                                  const float* __restrict__ w_dua,
                                                  const float* __restrict__ w_dla) {
    extern __shared__ u32 smemu[];
    u32*   Wh   = smemu;              // [2 mtile][16 ks16][32 lane][4] = 4096 (fp16x2)
    float* hbuf = (float*)(smemu + 4096);  // K1_STAGES x HBUF floats

    const int tid = threadIdx.x;
    const int w   = tid >> 5;
    const int l   = tid & 31;
    const int bid = blockIdx.x;       // 0..127; chunks c = bid + 128*i, i<4

    // ---- weight prep: fp16, pre-swizzled into m16n8k16 A-frag order ----
    for (int sidx = tid; sidx < 1024; sidx += 256) {
        int t = sidx >> 9, rem = sidx & 511, s = rem >> 5, ln = rem & 31;
#pragma unroll
        for (int r = 0; r < 4; r++) {
            int row = 16 * t + (ln >> 2) + 8 * (r & 1);
            int k0  = 16 * s + (ln & 3) * 2 + 8 * (r >> 1);
            float v0 = 0.f, v1 = 0.f;
            if (row < 20)       { v0 = w_pdp1[row * 276 + k0]; v1 = w_pdp1[row * 276 + k0 + 1]; }
            else if (row == 20) { v0 = w_dua[k0]; v1 = w_dua[k0 + 1]; }
            else if (row == 21) { v0 = w_dla[k0]; v1 = w_dla[k0 + 1]; }
            Wh[sidx * 4 + r] = (f16b(v1) << 16) | f16b(v0);
        }
    }

    const int row  = tid >> 3;
    const int seg0 = tid & 7;
    auto issue_load = [&](int g) {
        const int c2  = bid + (g >> 3) * 128;
        const int n2  = c2 >> 6;
        const int hw2 = (c2 & 63) << 8;
        const int kk  = g & 7;
        const float* srcr = hfea + ((size_t)(n2 * CCH + kk * 32) + row) * HWV + hw2;
        float* dstr = hbuf + (g & 3) * HBUF + row * HROW;
#pragma unroll
        for (int j = 0; j < 8; j++) { int seg = seg0 + j * 8; cp16(dstr + seg * 4, srcr + seg * 4); }
    };

    issue_load(0); CP_COMMIT();
    issue_load(1); CP_COMMIT();
    issue_load(2); CP_COMMIT();
    __syncthreads();   // weights ready before first compute

    int gi = 0;
#pragma unroll 1
    for (int ci = 0; ci < 4; ci++) {
        const int c   = bid + ci * 128;
        const int n   = c >> 6;
        const int hw0 = (c & 63) << 8;

        float Cf[2][4][4];
#pragma unroll
        for (int t = 0; t < 2; t++)
#pragma unroll
            for (int nt = 0; nt < 4; nt++)
#pragma unroll
                for (int r = 0; r < 4; r++) Cf[t][nt][r] = 0.f;

#pragma unroll 1
        for (int kc = 0; kc < 8; kc++) {
            CP_WAIT2();
            __syncthreads();
            if (gi + 3 < 32) issue_load(gi + 3);
            CP_COMMIT();

            const float* hb = hbuf + (gi & 3) * HBUF;
#pragma unroll
            for (int ks = 0; ks < 2; ks++) {
                const int s = kc * 2 + ks;
                u32 ah[2][4];
#pragma unroll
                for (int t = 0; t < 2; t++) {
                    uint4 h4 = *(const uint4*)(Wh + ((t * 16 + s) * 32 + l) * 4);
                    ah[t][0] = h4.x; ah[t][1] = h4.y; ah[t][2] = h4.z; ah[t][3] = h4.w;
                }
                u32 bh[4][2];
                const int rb = (16 * ks + (l & 3) * 2) * HROW + (l >> 2);
#pragma unroll
                for (int nt = 0; nt < 4; nt++) {
                    const int idx = rb + w * 32 + nt * 8;
                    float f00 = hb[idx];
                    float f01 = hb[idx + HROW];
                    float f10 = hb[idx + 8 * HROW];
                    float f11 = hb[idx + 9 * HROW];
                    bh[nt][0] = cvt_f16x2(f01, f00);
                    bh[nt][1] = cvt_f16x2(f11, f10);
                }
#pragma unroll
                for (int t = 0; t < 2; t++)
#pragma unroll
                    for (int nt = 0; nt < 4; nt++)
                        mma_f16(Cf[t][nt], ah[t], bh[nt]);
            }
            gi++;
        }

        // ---- store: rows 0..21, float2 per lane ----
        float* ob = (float*)g_hacc;
        const int lr  = l >> 2;
        const int pxo = 2 * (l & 3);
        const size_t pbase = (size_t)n * HWV + hw0;
#pragma unroll
        for (int t = 0; t < 2; t++)
#pragma unroll
            for (int nt = 0; nt < 4; nt++) {
                const int px = w * 32 + nt * 8 + pxo;
                const int row0 = 16 * t + lr;
                if (row0 < 22) {
                    float2 v; v.x = Cf[t][nt][0]; v.y = Cf[t][nt][1];
                    *(float2*)(ob + (size_t)row0 * NPIX + pbase + px) = v;
                }
                const int row1 = 16 * t + lr + 8;
                if (row1 < 22) {
                    float2 v; v.x = Cf[t][nt][2]; v.y = Cf[t][nt][3];
                    *(float2*)(ob + (size_t)row1 * NPIX + pbase + px) = v;
                }
            }
    }
}

// ============================================================================
// Kernel 2: HID=10 graph ops, packed over the pixel pair (R12 version).
// ============================================================================

struct P27 {
    const float* a[27];
    float* out;
};

#define K2T 128

__global__ void __launch_bounds__(K2T, 4) k2_kernel(P27 p) {
    const float* g_xhu  = p.a[1];
    const float* g_xhl  = p.a[2];
    const float* g_xf   = p.a[3];
    const float* g_xp   = p.a[4];
    const float* w_pdp1 = p.a[5];
    const float* w_pdp2 = p.a[6];
    const float* w_att  = p.a[7];
    const float* b_att  = p.a[8];
    const float* w_cua  = p.a[9];
    const float* b_cua  = p.a[10];
    const float* w_cu   = p.a[11];
    const float* w_cla  = p.a[12];
    const float* b_cla  = p.a[13];
    const float* w_cl   = p.a[14];
    const float* w_dua  = p.a[15];
    const float* b_dua  = p.a[16];
    const float* w_du   = p.a[17];
    const float* w_dla  = p.a[18];
    const float* b_dla  = p.a[19];
    const float* w_dl   = p.a[20];
    const float* w_ugu  = p.a[21];
    const float* b_ugu  = p.a[22];
    const float* w_ucu  = p.a[23];
    const float* w_ugl  = p.a[24];
    const float* b_ugl  = p.a[25];
    const float* w_ucl  = p.a[26];
    float* out = p.out;

    __shared__ __align__(16) u64 s_small[2152];
    __shared__ u64 s_dpu[K2T * 11];

    const int tid = threadIdx.x;
    {
        for (int i = tid; i < 400; i += K2T) { int o = i / 20, k = i % 20; s_small[i] = dup2(w_pdp1[o * 276 + 256 + k]); }
        for (int i = tid; i < 200; i += K2T) s_small[400 + i] = dup2(w_pdp2[i]);
        for (int i = tid; i < 22;  i += K2T) s_small[600 + i] = (i < 20) ? dup2(w_att[i]) : dup2(b_att[i - 20]);
        for (int i = tid; i < 44;  i += K2T) s_small[622 + i] = (i < 40) ? dup2(w_cua[i]) : dup2(b_cua[i - 40]);
        for (int i = tid; i < 200; i += K2T) s_small[666 + i] = dup2(w_cu[i]);
        for (int i = tid; i < 22;  i += K2T) s_small[866 + i] = (i < 20) ? dup2(w_cla[i]) : dup2(b_cla[i - 20]);
        for (int i = tid; i < 200; i += K2T) s_small[888 + i] = dup2(w_cl[i]);
        for (int i = tid; i < 21;  i += K2T) s_small[1088 + i] = (i < 20) ? dup2(w_dua[256 + i]) : dup2(b_dua[0]);
        for (int i = tid; i < 100; i += K2T) s_small[1110 + i] = dup2(w_du[i]);
        for (int i = tid; i < 21;  i += K2T) s_small[1210 + i] = (i < 20) ? dup2(w_dla[256 + i]) : dup2(b_dla[0]);
        for (int i = tid; i < 100; i += K2T) s_small[1232 + i] = dup2(w_dl[i]);
        for (int i = tid; i < 210; i += K2T) s_small[1332 + i] = (i < 200) ? dup2(w_ugu[i]) : dup2(b_ugu[i - 200]);
        for (int i = tid; i < 200; i += K2T) s_small[1542 + i] = dup2(w_ucu[i]);
        for (int i = tid; i < 210; i += K2T) s_small[1742 + i] = (i < 200) ? dup2(w_ugl[i]) : dup2(b_ugl[i - 200]);
        for (int i = tid; i < 200; i += K2T) s_small[1952 + i] = dup2(w_ucl[i]);
    }
    __syncthreads();

    const int pair = blockIdx.x * K2T + tid;
    const int pix  = pair * 2;
    const int n    = pix >> 14;
    const int hw   = pix & (HWV - 1);
    const size_t vb = (size_t)n * HIDN * HWV + hw;
    const u64* hac = g_hacc + pair;

    u64 xu[10], xl[10];
#pragma unroll
    for (int i = 0; i < 10; i++) {
        xu[i] = *(const u64*)(g_xhu + vb + (size_t)i * HWV);
        xl[i] = *(const u64*)(g_xhl + vb + (size_t)i * HWV);
    }

    u64 dpl[10];
    {
        u64 tt[20];
#pragma unroll
        for (int o = 0; o < 20; o++) {
            u64 a = hac[(size_t)o * NPAIR];
            const u64* wr = s_small + o * 20;
#pragma unroll
            for (int k = 0; k < 10; k += 2) {
                uu2 w = lds2(wr + k);
                a = ffma2(xu[k], w.x, a);
                a = ffma2(xu[k + 1], w.y, a);
            }
#pragma unroll
            for (int k = 0; k < 10; k += 2) {
                uu2 w = lds2(wr + 10 + k);
                a = ffma2(xl[k], w.x, a);
                a = ffma2(xl[k + 1], w.y, a);
            }
            tt[o] = relu2(a);
        }
#pragma unroll
        for (int o = 0; o < 10; o++) {
            u64 a = 0ULL, b = 0ULL;
#pragma unroll
            for (int i = 0; i < 10; i += 2) {
                uu2 wa = lds2(s_small + 400 + o * 10 + i);
                uu2 wb = lds2(s_small + 500 + o * 10 + i);
                a = ffma2(tt[i],      wa.x, a);
                a = ffma2(tt[i + 1],  wa.y, a);
                b = ffma2(tt[10 + i], wb.x, b);
                b = ffma2(tt[11 + i], wb.y, b);
            }
            s_dpu[tid * 11 + o] = relu2(a);
            dpl[o] = relu2(b);
        }
    }
    u64 agu, agl;
    {
        u64 a = s_small[620], b = s_small[621];
#pragma unroll
        for (int i = 0; i < 10; i += 2) {
            uu2 wa = lds2(s_small + 600 + i);
            uu2 wb = lds2(s_small + 610 + i);
            a = ffma2(xu[i], wa.x, a);
            a = ffma2(xu[i + 1], wa.y, a);
            b = ffma2(xl[i], wb.x, b);
            b = ffma2(xl[i + 1], wb.y, b);
        }
        agu = sigmoid2(a);
        agl = sigmoid2(b);
    }

    u64 xfv[10];
#pragma unroll
    for (int i = 0; i < 10; i++) xfv[i] = *(const u64*)(g_xf + vb + (size_t)i * HWV);

    // ================= U half =================
    {
        u64 msg[10];
#pragma unroll
        for (int i = 0; i < 10; i++) msg[i] = 0ULL;
#pragma unroll
        for (int pp = 0; pp < 4; pp++) {
            u64 xv[10];
            const float* xpp = g_xp + ((size_t)(pp * NIMG + n) * HIDN) * HWV + hw;
#pragma unroll
            for (int i = 0; i < 10; i++) xv[i] = *(const u64*)(xpp + (size_t)i * HWV);
            u64 s = s_small[662 + pp];
#pragma unroll
            for (int i = 0; i < 10; i += 2) {
                uu2 w = lds2(s_small + 622 + pp * 10 + i);
                s = ffma2(xv[i], w.x, s);
                s = ffma2(xv[i + 1], w.y, s);
            }
            u64 ca = sigmoid2(s);
#pragma unroll
            for (int i = 0; i < 10; i++) msg[i] = ffma2(xv[i], ca, msg[i]);
        }
        u64 m[10];
#pragma unroll
        for (int o = 0; o < 10; o++) {
            u64 a = 0ULL;
            const u64* wr = s_small + 666 + o * 20;
#pragma unroll
            for (int i = 0; i < 10; i += 2) {
                uu2 wa = lds2(wr + i);
                uu2 wb = lds2(wr + 10 + i);
                a = ffma2(xu[i],  wa.x, a);
                a = ffma2(xu[i + 1], wa.y, a);
                a = ffma2(msg[i], wb.x, a);
                a = ffma2(msg[i + 1], wb.y, a);
            }
            m[o] = relu2(a);
            m[o] = ffma2(dpl[o], agl, m[o]);
            m[o] = ffma2(xu[o],  agu, m[o]);
        }
        u64 attu;
        {
            u64 s = fadd2(hac[(size_t)20 * NPAIR], s_small[1108]);
#pragma unroll
            for (int i = 0; i < 10; i += 2) {
                uu2 wa = lds2(s_small + 1088 + i);
                uu2 wb = lds2(s_small + 1098 + i);
                s = ffma2(xfv[i], wa.x, s);
                s = ffma2(xfv[i + 1], wa.y, s);
                s = ffma2(xu[i],  wb.x, s);
                s = ffma2(xu[i + 1], wb.y, s);
            }
            attu = sigmoid2(s);
        }
        *(u64*)(out + OUT_ATTU + (size_t)n * HWV + hw) = attu;
        {
            u64 xfa[10];
#pragma unroll
            for (int i = 0; i < 10; i++) xfa[i] = fmul2(xfv[i], attu);
#pragma unroll
            for (int o = 0; o < 10; o++) {
                u64 a = 0ULL;
#pragma unroll
                for (int i = 0; i < 10; i += 2) {
                    uu2 w = lds2(s_small + 1110 + o * 10 + i);
                    a = ffma2(xfa[i], w.x, a);
                    a = ffma2(xfa[i + 1], w.y, a);
                }
                m[o] = fadd2(m[o], relu2(a));
            }
        }
#pragma unroll
        for (int o = 0; o < 10; o++) {
            u64 g  = s_small[1532 + o];
            u64 cd = 0ULL;
            const u64* wg = s_small + 1332 + o * 20;
            const u64* wc = s_small + 1542 + o * 20;
#pragma unroll
            for (int i = 0; i < 10; i += 2) {
                uu2 a1 = lds2(wg + i);
                uu2 a2 = lds2(wc + i);
                g  = ffma2(xu[i], a1.x, g);
                g  = ffma2(xu[i + 1], a1.y, g);
                cd = ffma2(xu[i], a2.x, cd);
                cd = ffma2(xu[i + 1], a2.y, cd);
            }
#pragma unroll
            for (int i = 0; i < 10; i += 2) {
                uu2 a1 = lds2(wg + 10 + i);
                uu2 a2 = lds2(wc + 10 + i);
                g  = ffma2(m[i], a1.x, g);
                g  = ffma2(m[i + 1], a1.y, g);
                cd = ffma2(m[i], a2.x, cd);
                cd = ffma2(m[i + 1], a2.y, cd);
            }
            g  = sigmoid2(g);
            cd = relu2(cd);
            u64 res = ffma2(g, fadd2(cd, neg2(xu[o])), xu[o]);
            *(u64*)(out + (size_t)(n * HIDN + o) * HWV + hw) = res;
        }
    }

    // ================= L half =================
    {
        u64 xlv[10], xf2[10];
#pragma unroll
        for (int i = 0; i < 10; i++) {
            xlv[i] = *(const u64*)(g_xhl + vb + (size_t)i * HWV);
            xf2[i] = *(const u64*)(g_xf  + vb + (size_t)i * HWV);
        }
        u64 msg[10];
#pragma unroll
        for (int i = 0; i < 10; i++) msg[i] = 0ULL;
#pragma unroll
        for (int pp = 0; pp < 2; pp++) {
            u64 xv[10];
            const float* xpp = g_xp + ((size_t)((4 + pp) * NIMG + n) * HIDN) * HWV + hw;
#pragma unroll
            for (int i = 0; i < 10; i++) xv[i] = *(const u64*)(xpp + (size_t)i * HWV);
            u64 s = s_small[886 + pp];
#pragma unroll
            for (int i = 0; i < 10; i += 2) {
                uu2 w = lds2(s_small + 866 + pp * 10 + i);
                s = ffma2(xv[i], w.x, s);
                s = ffma2(xv[i + 1], w.y, s);
            }
            u64 ca = sigmoid2(s);
#pragma unroll
            for (int i = 0; i < 10; i++) msg[i] = ffma2(xv[i], ca, msg[i]);
        }
        u64 m[10];
#pragma unroll
        for (int o = 0; o < 10; o++) {
            u64 a = 0ULL;
            const u64* wr = s_small + 888 + o * 20;
#pragma unroll
            for (int i = 0; i < 10; i += 2) {
                uu2 wa = lds2(wr + i);
                uu2 wb = lds2(wr + 10 + i);
                a = ffma2(xlv[i], wa.x, a);
                a = ffma2(xlv[i + 1], wa.y, a);
                a = ffma2(msg[i], wb.x, a);
                a = ffma2(msg[i + 1], wb.y, a);
            }
            m[o] = relu2(a);
            m[o] = ffma2(s_dpu[tid * 11 + o], agu, m[o]);
            m[o] = ffma2(xlv[o], agl, m[o]);
        }
        u64 attl;
        {
            u64 s = fadd2(hac[(size_t)21 * NPAIR], s_small[1230]);
#pragma unroll
            for (int i = 0; i < 10; i += 2) {
                uu2 wa = lds2(s_small + 1210 + i);
                uu2 wb = lds2(s_small + 1220 + i);
                s = ffma2(xf2[i], wa.x, s);
                s = ffma2(xf2[i + 1], wa.y, s);
                s = ffma2(xlv[i], wb.x, s);
                s = ffma2(xlv[i + 1], wb.y, s);
            }
            attl = sigmoid2(s);
        }
        *(u64*)(out + OUT_ATTL + (size_t)n * HWV + hw) = attl;
        {
            u64 xfa[10];
#pragma unroll
            for (int i = 0; i < 10; i++) xfa[i] = fmul2(xf2[i], attl);
#pragma unroll
            for (int o = 0; o < 10; o++) {
                u64 a = 0ULL;
#pragma unroll
                for (int i = 0; i < 10; i += 2) {
                    uu2 w = lds2(s_small + 1232 + o * 10 + i);
                    a = ffma2(xfa[i], w.x, a);
                    a = ffma2(xfa[i + 1], w.y, a);
                }
                m[o] = fadd2(m[o], relu2(a));
            }
        }
#pragma unroll
        for (int o = 0; o < 10; o++) {
            u64 g  = s_small[1942 + o];
            u64 cd = 0ULL;
            const u64* wg = s_small + 1742 + o * 20;
            const u64* wc = s_small + 1952 + o * 20;
#pragma unroll
            for (int i = 0; i < 10; i += 2) {
                uu2 a1 = lds2(wg + i);
                uu2 a2 = lds2(wc + i);
                g  = ffma2(xlv[i], a1.x, g);
                g  = ffma2(xlv[i + 1], a1.y, g);
                cd = ffma2(xlv[i], a2.x, cd);
                cd = ffma2(xlv[i + 1], a2.y, cd);
            }
#pragma unroll
            for (int i = 0; i < 10; i += 2) {
                uu2 a1 = lds2(wg + 10 + i);
                uu2 a2 = lds2(wc + 10 + i);
                g  = ffma2(m[i], a1.x, g);
                g  = ffma2(m[i + 1], a1.y, g);
                cd = ffma2(m[i], a2.x, cd);
                cd = ffma2(m[i + 1], a2.y, cd);
            }
            g  = sigmoid2(g);
            cd = relu2(cd);
            u64 res = ffma2(g, fadd2(cd, neg2(xlv[o])), xlv[o]);
            *(u64*)(out + OUT_XHL + (size_t)(n * HIDN + o) * HWV + hw) = res;
        }
    }
}

extern "C" void kernel_launch(void* const* d_in, const int* in_sizes, int n_in,
                              void* d_out, int out_size) {
    cudaFuncSetAttribute(k1t_kernel, cudaFuncAttributeMaxDynamicSharedMemorySize,
                         K1_SMEM_BYTES);
    k1t_kernel<<<128, 256, K1_SMEM_BYTES>>>((const float*)d_in[0], (const float*)d_in[5],
                                            (const float*)d_in[15], (const float*)d_in[18]);
    P27 p;
    for (int i = 0; i < 27; i++) p.a[i] = (const float*)d_in[i];
    p.out = (float*)d_out;
    k2_kernel<<<512, K2T>>>(p);
}